// round 6
// baseline (speedup 1.0000x reference)
#include <cuda_runtime.h>
#include <cuda_bf16.h>

#ifndef S_SCALE
#define S_SCALE 64.0f
#endif
#ifndef MARGIN
#define MARGIN 0.35f
#endif

// S * log2(e): exp(S*x) == exp2(K*x) with a single FMUL before MUFU.EX2
#define K_EXP2 (S_SCALE * 1.4426950408889634f)

__device__ float        g_sum;     // zero at module load; reset by last CTA each launch
__device__ unsigned int g_count;   // self-resetting via atomicInc wrap

// One CTA per row, 256 threads: whole grid resident in a single wave
// (7 CTAs/SM x 8 warps = 56 warps <= 64), so DRAM pressure stays uniform.
__global__ __launch_bounds__(256) void row_loss_kernel(
    const float* __restrict__ x,
    const int* __restrict__ label,   // int32 (JAX demotes int64 without x64 mode)
    float* __restrict__ out,
    int C, int B)
{
    const int row = blockIdx.x;
    const size_t base = (size_t)row * (size_t)C;
    const float4* __restrict__ x4 = reinterpret_cast<const float4*>(x + base);
    const int n4 = C >> 2;               // 25000 for C=100000
    const int stride = blockDim.x;

    float s = 0.0f;

    // 4-deep unrolled main loop: 4 outstanding LDG.128 per thread.
    int i = threadIdx.x;
    const int n4_4 = n4 - 3 * stride;
    for (; i < n4_4; i += 4 * stride) {
        float4 a = __ldcs(&x4[i]);
        float4 b = __ldcs(&x4[i + stride]);
        float4 c = __ldcs(&x4[i + 2 * stride]);
        float4 d = __ldcs(&x4[i + 3 * stride]);
        s += exp2f(K_EXP2 * a.x) + exp2f(K_EXP2 * a.y)
           + exp2f(K_EXP2 * a.z) + exp2f(K_EXP2 * a.w);
        s += exp2f(K_EXP2 * b.x) + exp2f(K_EXP2 * b.y)
           + exp2f(K_EXP2 * b.z) + exp2f(K_EXP2 * b.w);
        s += exp2f(K_EXP2 * c.x) + exp2f(K_EXP2 * c.y)
           + exp2f(K_EXP2 * c.z) + exp2f(K_EXP2 * c.w);
        s += exp2f(K_EXP2 * d.x) + exp2f(K_EXP2 * d.y)
           + exp2f(K_EXP2 * d.z) + exp2f(K_EXP2 * d.w);
    }
    for (; i < n4; i += stride) {
        float4 a = __ldcs(&x4[i]);
        s += exp2f(K_EXP2 * a.x) + exp2f(K_EXP2 * a.y)
           + exp2f(K_EXP2 * a.z) + exp2f(K_EXP2 * a.w);
    }
    // scalar tail (C % 4) — not taken for C=100000 but keep it correct
    for (int j = (n4 << 2) + threadIdx.x; j < C; j += stride) {
        s += exp2f(K_EXP2 * x[base + j]);
    }

    // block reduction: warp shuffle then cross-warp via shared
    __shared__ float red[8];
    #pragma unroll
    for (int o = 16; o > 0; o >>= 1)
        s += __shfl_down_sync(0xffffffffu, s, o);
    if ((threadIdx.x & 31) == 0) red[threadIdx.x >> 5] = s;
    __syncthreads();
    if (threadIdx.x < 32) {
        float v = (threadIdx.x < (stride >> 5)) ? red[threadIdx.x] : 0.0f;
        #pragma unroll
        for (int o = 4; o > 0; o >>= 1)
            v += __shfl_down_sync(0xffffffffu, v, o);
        if (threadIdx.x == 0) {
            int lbl = label[row];
            lbl = (lbl < 0) ? 0 : ((lbl >= C) ? C - 1 : lbl);   // defensive clamp
            const float xy = x[base + (size_t)lbl];
            const float num = S_SCALE * (xy - MARGIN);
            const float sum_excl = v - exp2f(K_EXP2 * xy);
            const float denom = __expf(num) + sum_excl;
            const float L = (num - logf(denom)) / S_SCALE;

            // fold into global mean; last CTA publishes and resets
            atomicAdd(&g_sum, L);
            __threadfence();
            unsigned t = atomicInc(&g_count, gridDim.x - 1); // wraps to 0 at last
            if (t == gridDim.x - 1) {
                out[0] = -g_sum / (float)B;
                g_sum = 0.0f;      // ready for next graph replay
            }
        }
    }
}

extern "C" void kernel_launch(void* const* d_in, const int* in_sizes, int n_in,
                              void* d_out, int out_size)
{
    const float* x     = (const float*)d_in[0];
    const int*   label = (const int*)d_in[1];
    float*       out   = (float*)d_out;

    const int B = in_sizes[1];            // rows = number of labels
    const int C = in_sizes[0] / B;        // columns

    row_loss_kernel<<<B, 256>>>(x, label, out, C, B);
}

// round 7
// speedup vs baseline: 1.1493x; 1.1493x over previous
#include <cuda_runtime.h>
#include <cuda_bf16.h>

#ifndef S_SCALE
#define S_SCALE 64.0f
#endif
#ifndef MARGIN
#define MARGIN 0.35f
#endif

// S * log2(e): exp(S*x) == exp2(K*x), single FMUL before MUFU.EX2
#define K_EXP2 (S_SCALE * 1.4426950408889634f)

#define GRID_CTAS 592          // 148 SMs x 4 CTAs -> exactly one wave
#define NTHREADS  512
#define MAX_B     4096

__device__ float        g_rowsum[MAX_B];  // zero at load; reset by epilogue each launch
__device__ unsigned int g_count;          // self-resetting via atomicInc wrap

__global__ __launch_bounds__(NTHREADS, 4) void loss_kernel(
    const float* __restrict__ x,
    const int* __restrict__ label,   // int32 (JAX demotes int64 without x64 mode)
    float* __restrict__ out,
    int C, int B)
{
    const int tid = threadIdx.x;
    const size_t total = (size_t)B * (size_t)C;
    // equal chunks, rounded to float4 granularity
    const size_t chunk = (((total + GRID_CTAS - 1) / GRID_CTAS) + 3) & ~(size_t)3;
    const size_t cbeg = (size_t)blockIdx.x * chunk;
    const size_t cend = (cbeg + chunk < total) ? (cbeg + chunk) : total;

    __shared__ float red[16];

    if (cbeg < total) {
        const int r0 = (int)(cbeg / (size_t)C);
        const int r1 = (int)((cend - 1) / (size_t)C);
        for (int r = r0; r <= r1; ++r) {
            const size_t rowbeg = (size_t)r * (size_t)C;
            const size_t a = (cbeg > rowbeg) ? cbeg : rowbeg;
            const size_t b = (cend < rowbeg + C) ? cend : rowbeg + C;

            float s = 0.0f;
            // alignment-safe split: scalar prefix, float4 body, scalar suffix
            const size_t a4 = (a + 3) & ~(size_t)3;
            const size_t b4 = b & ~(size_t)3;

            for (size_t j = a + tid; j < a4 && j < b; j += NTHREADS)
                s += exp2f(K_EXP2 * x[j]);

            if (b4 > a4) {
                const float4* __restrict__ p = reinterpret_cast<const float4*>(x + a4);
                const int n4 = (int)((b4 - a4) >> 2);
                int i = tid;
                const int n4_4 = n4 - 3 * NTHREADS;
                for (; i < n4_4; i += 4 * NTHREADS) {
                    float4 va = __ldcs(&p[i]);
                    float4 vb = __ldcs(&p[i + NTHREADS]);
                    float4 vc = __ldcs(&p[i + 2 * NTHREADS]);
                    float4 vd = __ldcs(&p[i + 3 * NTHREADS]);
                    s += exp2f(K_EXP2 * va.x) + exp2f(K_EXP2 * va.y)
                       + exp2f(K_EXP2 * va.z) + exp2f(K_EXP2 * va.w);
                    s += exp2f(K_EXP2 * vb.x) + exp2f(K_EXP2 * vb.y)
                       + exp2f(K_EXP2 * vb.z) + exp2f(K_EXP2 * vb.w);
                    s += exp2f(K_EXP2 * vc.x) + exp2f(K_EXP2 * vc.y)
                       + exp2f(K_EXP2 * vc.z) + exp2f(K_EXP2 * vc.w);
                    s += exp2f(K_EXP2 * vd.x) + exp2f(K_EXP2 * vd.y)
                       + exp2f(K_EXP2 * vd.z) + exp2f(K_EXP2 * vd.w);
                }
                for (; i < n4; i += NTHREADS) {
                    float4 va = __ldcs(&p[i]);
                    s += exp2f(K_EXP2 * va.x) + exp2f(K_EXP2 * va.y)
                       + exp2f(K_EXP2 * va.z) + exp2f(K_EXP2 * va.w);
                }
            }

            for (size_t j = b4 + tid; j < b; j += NTHREADS)
                if (j >= a4) s += exp2f(K_EXP2 * x[j]);

            // block reduce -> one atomic per row-segment
            #pragma unroll
            for (int o = 16; o > 0; o >>= 1)
                s += __shfl_down_sync(0xffffffffu, s, o);
            if ((tid & 31) == 0) red[tid >> 5] = s;
            __syncthreads();
            if (tid < 32) {
                float v = (tid < (NTHREADS >> 5)) ? red[tid] : 0.0f;
                #pragma unroll
                for (int o = 8; o > 0; o >>= 1)
                    v += __shfl_down_sync(0xffffffffu, v, o);
                if (tid == 0)
                    atomicAdd(&g_rowsum[r], v);
            }
            __syncthreads();   // red[] reused next segment
        }
    }

    // ---- completion counter: last CTA runs the epilogue ----
    __shared__ int is_last;
    if (tid == 0) {
        __threadfence();
        unsigned t = atomicInc(&g_count, GRID_CTAS - 1);  // wraps to 0 at last
        is_last = (t == GRID_CTAS - 1);
    }
    __syncthreads();
    if (!is_last) return;

    // epilogue: per-row loss + mean, then reset g_rowsum for the next replay
    float ls = 0.0f;
    for (int r = tid; r < B; r += NTHREADS) {
        int lbl = label[r];
        lbl = (lbl < 0) ? 0 : ((lbl >= C) ? C - 1 : lbl);   // defensive clamp
        const float xy = x[(size_t)r * (size_t)C + (size_t)lbl];
        const float v  = g_rowsum[r];
        g_rowsum[r] = 0.0f;
        const float num = S_SCALE * (xy - MARGIN);
        const float denom = __expf(num) + (v - exp2f(K_EXP2 * xy));
        ls += (num - logf(denom));
    }
    #pragma unroll
    for (int o = 16; o > 0; o >>= 1)
        ls += __shfl_down_sync(0xffffffffu, ls, o);
    if ((tid & 31) == 0) red[tid >> 5] = ls;
    __syncthreads();
    if (tid < 32) {
        float v = (tid < (NTHREADS >> 5)) ? red[tid] : 0.0f;
        #pragma unroll
        for (int o = 8; o > 0; o >>= 1)
            v += __shfl_down_sync(0xffffffffu, v, o);
        if (tid == 0)
            out[0] = -v / (S_SCALE * (float)B);
    }
}

extern "C" void kernel_launch(void* const* d_in, const int* in_sizes, int n_in,
                              void* d_out, int out_size)
{
    const float* x     = (const float*)d_in[0];
    const int*   label = (const int*)d_in[1];
    float*       out   = (float*)d_out;

    const int B = in_sizes[1];            // rows = number of labels
    const int C = in_sizes[0] / B;        // columns

    loss_kernel<<<GRID_CTAS, NTHREADS>>>(x, label, out, C, B);
}